// round 4
// baseline (speedup 1.0000x reference)
#include <cuda_runtime.h>
#include <cuda_bf16.h>
#include <math.h>

// Problem constants
// N=16384 nodes, L=8 chain, D=256 in, H=256 hidden, R=64 rel
// Gate order (PyTorch): i, f, g, o

#define NTHREADS 256
#define BM 128
#define BN 128
#define BK 32

// Scratch (device globals — allocation-free rule)
__device__ float g_X[268435456];  // [2][8][16384][1024] : Xpre = x@Wih^T + (bih+bhh)
__device__ float g_h[16777216];   // [2 lstm][2 buf][16384][256]
__device__ float g_c[8388608];    // [2 lstm][16384][256]

struct SmemGemm {
  __nv_bfloat16 a_hi[BM][BK + 2];
  __nv_bfloat16 a_lo[BM][BK + 2];
  __nv_bfloat16 b_hi[BN][BK + 2];
  __nv_bfloat16 b_lo[BN][BK + 2];
};
union SmemU {
  SmemGemm g;
  float ep[64 * 132];  // epilogue half-tile (64 rows x 128 cols, padded stride 132)
};

__device__ __forceinline__ void mma16816(float* d, const unsigned* a, const unsigned* b) {
  asm volatile(
      "mma.sync.aligned.m16n8k16.row.col.f32.bf16.bf16.f32 "
      "{%0,%1,%2,%3}, {%4,%5,%6,%7}, {%8,%9}, {%0,%1,%2,%3};\n"
      : "+f"(d[0]), "+f"(d[1]), "+f"(d[2]), "+f"(d[3])
      : "r"(a[0]), "r"(a[1]), "r"(a[2]), "r"(a[3]), "r"(b[0]), "r"(b[1]));
}

// fp32 -> (hi, lo) bf16 split; 3 cross-products recover ~16-bit mantissa accuracy
__device__ __forceinline__ void split4(float4 v, __nv_bfloat16* hi, __nv_bfloat16* lo) {
  float x[4] = {v.x, v.y, v.z, v.w};
#pragma unroll
  for (int q = 0; q < 4; q++) {
    __nv_bfloat16 h = __float2bfloat16(x[q]);
    hi[q] = h;
    lo[q] = __float2bfloat16(x[q] - __bfloat162float(h));
  }
}

__device__ __forceinline__ float sigmoidf_(float x) { return 1.0f / (1.0f + expf(-x)); }

// One BK-chunk of the 128x128 warp-tiled GEMM (8 warps: wm in {0,1} x wn in {0..3};
// warp tile 64x32 = 4x4 m16n8 fragments). acc += Ahi*Bhi + Ahi*Blo + Alo*Bhi.
__device__ __forceinline__ void gemm_chunk(const SmemGemm& s, float acc[4][4][4],
                                           int wm, int wn, int lane) {
  const int qr = lane >> 2;
  const int qc = (lane & 3) << 1;
#pragma unroll
  for (int kk = 0; kk < BK; kk += 16) {
    unsigned ah[4][4], al[4][4], bh[4][2], bl[4][2];
#pragma unroll
    for (int mi = 0; mi < 4; mi++) {
      int r = wm * 64 + mi * 16 + qr;
      ah[mi][0] = *(const unsigned*)&s.a_hi[r][kk + qc];
      ah[mi][1] = *(const unsigned*)&s.a_hi[r + 8][kk + qc];
      ah[mi][2] = *(const unsigned*)&s.a_hi[r][kk + qc + 8];
      ah[mi][3] = *(const unsigned*)&s.a_hi[r + 8][kk + qc + 8];
      al[mi][0] = *(const unsigned*)&s.a_lo[r][kk + qc];
      al[mi][1] = *(const unsigned*)&s.a_lo[r + 8][kk + qc];
      al[mi][2] = *(const unsigned*)&s.a_lo[r][kk + qc + 8];
      al[mi][3] = *(const unsigned*)&s.a_lo[r + 8][kk + qc + 8];
    }
#pragma unroll
    for (int ni = 0; ni < 4; ni++) {
      int c = wn * 32 + ni * 8 + qr;
      bh[ni][0] = *(const unsigned*)&s.b_hi[c][kk + qc];
      bh[ni][1] = *(const unsigned*)&s.b_hi[c][kk + qc + 8];
      bl[ni][0] = *(const unsigned*)&s.b_lo[c][kk + qc];
      bl[ni][1] = *(const unsigned*)&s.b_lo[c][kk + qc + 8];
    }
#pragma unroll
    for (int mi = 0; mi < 4; mi++)
#pragma unroll
      for (int ni = 0; ni < 4; ni++) {
        mma16816(acc[mi][ni], ah[mi], bh[ni]);
        mma16816(acc[mi][ni], ah[mi], bl[ni]);
        mma16816(acc[mi][ni], al[mi], bh[ni]);
      }
  }
}

// Store one 64-row half (phase p) of the accumulator tile into su.ep
__device__ __forceinline__ void store_acc_phase(SmemU& su, float acc[4][4][4],
                                                int wm, int wn, int lane, int p) {
  if (wm == p) {
    const int qr = lane >> 2;
    const int qc = (lane & 3) << 1;
#pragma unroll
    for (int mi = 0; mi < 4; mi++)
#pragma unroll
      for (int ni = 0; ni < 4; ni++) {
        int rr = mi * 16 + qr;
        int cc = wn * 32 + ni * 8 + qc;
        su.ep[rr * 132 + cc] = acc[mi][ni][0];
        su.ep[rr * 132 + cc + 1] = acc[mi][ni][1];
        su.ep[(rr + 8) * 132 + cc] = acc[mi][ni][2];
        su.ep[(rr + 8) * 132 + cc + 1] = acc[mi][ni][3];
      }
  }
}

// ---------------------------------------------------------------------------
// Kernel 1: Xpre[z][l][n][4H] = x[z][n][l][:] @ Wih_z^T + (bih_z + bhh_z)
// grid: (colTile=8, rowTile=1024, z=2), rows indexed r = n*8 + l over [N*L]
// ---------------------------------------------------------------------------
__global__ __launch_bounds__(NTHREADS, 1) void k_precompute(
    const float* __restrict__ xl, const float* __restrict__ xr,
    const float* __restrict__ Wih_l, const float* __restrict__ Wih_r,
    const float* __restrict__ bih_l, const float* __restrict__ bhh_l,
    const float* __restrict__ bih_r, const float* __restrict__ bhh_r) {
  __shared__ SmemU su;
  const int tid = threadIdx.x;
  const int z = blockIdx.z;
  const int colTile = blockIdx.x;
  const long rowBase = (long)blockIdx.y * BM;
  const float* A = z ? xr : xl;
  const float* B = z ? Wih_r : Wih_l;
  const float* bi = z ? bih_r : bih_l;
  const float* bhb = z ? bhh_r : bhh_l;

  const int wid = tid >> 5, lane = tid & 31;
  const int wm = wid & 1, wn = wid >> 1;

  float acc[4][4][4];
#pragma unroll
  for (int a = 0; a < 4; a++)
#pragma unroll
    for (int b = 0; b < 4; b++)
#pragma unroll
      for (int q = 0; q < 4; q++) acc[a][b][q] = 0.0f;

  for (int k0 = 0; k0 < 256; k0 += BK) {
#pragma unroll
    for (int i = 0; i < 4; i++) {
      int f = tid + i * NTHREADS;  // float4 index in 128x32 tile
      int r = f >> 3;
      int c = (f & 7) << 2;
      float4 va = *(const float4*)(A + (rowBase + r) * 256 + k0 + c);
      split4(va, &su.g.a_hi[r][c], &su.g.a_lo[r][c]);
      float4 vb = *(const float4*)(B + (long)(colTile * 128 + r) * 256 + k0 + c);
      split4(vb, &su.g.b_hi[r][c], &su.g.b_lo[r][c]);
    }
    __syncthreads();
    gemm_chunk(su.g, acc, wm, wn, lane);
    __syncthreads();
  }

  for (int p = 0; p < 2; p++) {
    store_acc_phase(su, acc, wm, wn, lane, p);
    __syncthreads();
#pragma unroll
    for (int i = 0; i < 8; i++) {
      int f = tid + i * NTHREADS;  // float4 index in 64x128
      int rl = f >> 5;
      int c4 = (f & 31) << 2;
      float4 v = *(const float4*)&su.ep[rl * 132 + c4];
      int col = colTile * 128 + c4;
      v.x += bi[col] + bhb[col];
      v.y += bi[col + 1] + bhb[col + 1];
      v.z += bi[col + 2] + bhb[col + 2];
      v.w += bi[col + 3] + bhb[col + 3];
      long rg = rowBase + p * 64 + rl;
      long n = rg >> 3;
      int l = (int)(rg & 7);
      *(float4*)(g_X + (((long)z * 8 + l) * 16384 + n) * 1024 + col) = v;
    }
    __syncthreads();
  }
}

// ---------------------------------------------------------------------------
// Kernel 2: step 0 elementwise (h0 = c0 = 0): c = sig(i)*tanh(g); h = sig(o)*tanh(c)
// ---------------------------------------------------------------------------
__global__ void k_step0() {
  long idx = (long)blockIdx.x * 256 + threadIdx.x;  // [0, 2*16384*256)
  long z = idx >> 22;
  long e = idx & 4194303;  // n*256 + j
  long n = e >> 8;
  int j = (int)(e & 255);
  const float* xpre = g_X + z * 8L * 16384 * 1024;
  long xb = n * 1024 + j;
  float gi = xpre[xb];
  float gg = xpre[xb + 512];
  float go = xpre[xb + 768];
  float cn = sigmoidf_(gi) * tanhf(gg);
  g_c[z * 4194304 + e] = cn;
  g_h[(z * 2 + 1) * 4194304 + e] = sigmoidf_(go) * tanhf(cn);
}

// ---------------------------------------------------------------------------
// Kernel 3: recurrent step t (t=1..7): gates = h_{t-1}@Whh^T + Xpre[t]; cell update.
// grid: (strip=8, rowTile=128, z=2). CTA gate-column tile = 4 gates x 32 hidden units.
// h double-buffered: read buf[t&1], write buf[(t+1)&1]; c in place.
// ---------------------------------------------------------------------------
__global__ __launch_bounds__(NTHREADS, 1) void k_step(
    const float* __restrict__ Whh_l, const float* __restrict__ Whh_r, int t) {
  __shared__ SmemU su;
  const int tid = threadIdx.x;
  const int z = blockIdx.z;
  const int strip = blockIdx.x;
  const long rowBase = (long)blockIdx.y * BM;
  const float* B = z ? Whh_r : Whh_l;
  const float* hprev = g_h + ((long)z * 2 + (t & 1)) * 4194304;
  float* hnext = g_h + ((long)z * 2 + ((t + 1) & 1)) * 4194304;
  float* cst = g_c + (long)z * 4194304;
  const float* xpre = g_X + ((long)z * 8 + t) * 16384L * 1024;

  const int wid = tid >> 5, lane = tid & 31;
  const int wm = wid & 1, wn = wid >> 1;

  float acc[4][4][4];
#pragma unroll
  for (int a = 0; a < 4; a++)
#pragma unroll
    for (int b = 0; b < 4; b++)
#pragma unroll
      for (int q = 0; q < 4; q++) acc[a][b][q] = 0.0f;

  for (int k0 = 0; k0 < 256; k0 += BK) {
#pragma unroll
    for (int i = 0; i < 4; i++) {
      int f = tid + i * NTHREADS;
      int r = f >> 3;
      int c = (f & 7) << 2;
      float4 va = *(const float4*)(hprev + (rowBase + r) * 256 + k0 + c);
      split4(va, &su.g.a_hi[r][c], &su.g.a_lo[r][c]);
      // B tile row r -> Whh row = gate*256 + strip*32 + (r&31)
      long brow = (long)((r >> 5) << 8) + strip * 32 + (r & 31);
      float4 vb = *(const float4*)(B + brow * 256 + k0 + c);
      split4(vb, &su.g.b_hi[r][c], &su.g.b_lo[r][c]);
    }
    __syncthreads();
    gemm_chunk(su.g, acc, wm, wn, lane);
    __syncthreads();
  }

  for (int p = 0; p < 2; p++) {
    store_acc_phase(su, acc, wm, wn, lane, p);
    __syncthreads();
#pragma unroll
    for (int i = 0; i < 8; i++) {
      int e = tid + i * NTHREADS;  // 64 rows x 32 hidden units
      int rl = e >> 5;
      int jj = e & 31;
      long n = rowBase + p * 64 + rl;
      int j = strip * 32 + jj;
      long xb = n * 1024 + j;
      float gi = su.ep[rl * 132 + jj] + xpre[xb];
      float gf = su.ep[rl * 132 + 32 + jj] + xpre[xb + 256];
      float gg = su.ep[rl * 132 + 64 + jj] + xpre[xb + 512];
      float go = su.ep[rl * 132 + 96 + jj] + xpre[xb + 768];
      float cn = sigmoidf_(gf) * cst[n * 256 + j] + sigmoidf_(gi) * tanhf(gg);
      cst[n * 256 + j] = cn;
      hnext[n * 256 + j] = sigmoidf_(go) * tanhf(cn);
    }
    __syncthreads();
  }
}

// ---------------------------------------------------------------------------
// Kernel 4: encoder out = tanh([hl, hr, rel] @ Wenc^T + benc)
// grid: (colTile=2, rowTile=128). K = 576 gathered from 3 sources.
// Final h lives in buf 0 for both LSTMs (after t=7 write).
// ---------------------------------------------------------------------------
__global__ __launch_bounds__(NTHREADS, 1) void k_enc(
    const float* __restrict__ rel, const float* __restrict__ Wenc,
    const float* __restrict__ benc, float* __restrict__ out) {
  __shared__ SmemU su;
  const int tid = threadIdx.x;
  const int colTile = blockIdx.x;
  const long rowBase = (long)blockIdx.y * BM;
  const float* hL = g_h;                   // z=0, buf 0
  const float* hR = g_h + 2L * 4194304;    // z=1, buf 0

  const int wid = tid >> 5, lane = tid & 31;
  const int wm = wid & 1, wn = wid >> 1;

  float acc[4][4][4];
#pragma unroll
  for (int a = 0; a < 4; a++)
#pragma unroll
    for (int b = 0; b < 4; b++)
#pragma unroll
      for (int q = 0; q < 4; q++) acc[a][b][q] = 0.0f;

  for (int k0 = 0; k0 < 576; k0 += BK) {
    const float* Asrc;
    long lda, koff;
    if (k0 < 256) {
      Asrc = hL; lda = 256; koff = k0;
    } else if (k0 < 512) {
      Asrc = hR; lda = 256; koff = k0 - 256;
    } else {
      Asrc = rel; lda = 64; koff = k0 - 512;
    }
#pragma unroll
    for (int i = 0; i < 4; i++) {
      int f = tid + i * NTHREADS;
      int r = f >> 3;
      int c = (f & 7) << 2;
      float4 va = *(const float4*)(Asrc + (rowBase + r) * lda + koff + c);
      split4(va, &su.g.a_hi[r][c], &su.g.a_lo[r][c]);
      float4 vb = *(const float4*)(Wenc + (long)(colTile * 128 + r) * 576 + k0 + c);
      split4(vb, &su.g.b_hi[r][c], &su.g.b_lo[r][c]);
    }
    __syncthreads();
    gemm_chunk(su.g, acc, wm, wn, lane);
    __syncthreads();
  }

  for (int p = 0; p < 2; p++) {
    store_acc_phase(su, acc, wm, wn, lane, p);
    __syncthreads();
#pragma unroll
    for (int i = 0; i < 8; i++) {
      int f = tid + i * NTHREADS;
      int rl = f >> 5;
      int c4 = (f & 31) << 2;
      float4 v = *(const float4*)&su.ep[rl * 132 + c4];
      int col = colTile * 128 + c4;
      v.x = tanhf(v.x + benc[col]);
      v.y = tanhf(v.y + benc[col + 1]);
      v.z = tanhf(v.z + benc[col + 2]);
      v.w = tanhf(v.w + benc[col + 3]);
      long n = rowBase + p * 64 + rl;
      *(float4*)(out + n * 256 + col) = v;
    }
    __syncthreads();
  }
}

// ---------------------------------------------------------------------------
extern "C" void kernel_launch(void* const* d_in, const int* in_sizes, int n_in,
                              void* d_out, int out_size) {
  (void)in_sizes; (void)n_in; (void)out_size;
  const float* left  = (const float*)d_in[0];
  const float* right = (const float*)d_in[1];
  const float* rel   = (const float*)d_in[2];
  const float* Wih_l = (const float*)d_in[3];
  const float* Whh_l = (const float*)d_in[4];
  const float* bih_l = (const float*)d_in[5];
  const float* bhh_l = (const float*)d_in[6];
  const float* Wih_r = (const float*)d_in[7];
  const float* Whh_r = (const float*)d_in[8];
  const float* bih_r = (const float*)d_in[9];
  const float* bhh_r = (const float*)d_in[10];
  const float* Wenc  = (const float*)d_in[11];
  const float* benc  = (const float*)d_in[12];
  float* out = (float*)d_out;

  k_precompute<<<dim3(8, 1024, 2), NTHREADS>>>(left, right, Wih_l, Wih_r,
                                               bih_l, bhh_l, bih_r, bhh_r);
  k_step0<<<32768, 256>>>();
  for (int t = 1; t < 8; t++)
    k_step<<<dim3(8, 128, 2), NTHREADS>>>(Whh_l, Whh_r, t);
  k_enc<<<dim3(2, 128), NTHREADS>>>(rel, Wenc, benc, out);
}

// round 5
// speedup vs baseline: 1.0150x; 1.0150x over previous
#include <cuda_runtime.h>
#include <cuda_bf16.h>
#include <math.h>

// Problem constants
// N=16384 nodes, L=8 chain, D=256 in, H=256 hidden, R=64 rel
// Gate order (PyTorch): i, f, g, o

#define NTHREADS 256
#define BM 128
#define BN 128
#define BK 32

// Scratch (device globals — allocation-free rule)
__device__ float g_X[268435456];  // [2][8][16384][1024] : Xpre = x@Wih^T + (bih+bhh)
__device__ float g_h[16777216];   // [2 lstm][2 buf][16384][256]
__device__ float g_c[8388608];    // [2 lstm][16384][256]

struct SmemGemm {
  __nv_bfloat16 a_hi[BM][BK + 2];
  __nv_bfloat16 a_lo[BM][BK + 2];
  __nv_bfloat16 b_hi[BN][BK + 2];
  __nv_bfloat16 b_lo[BN][BK + 2];
};
union SmemU {
  SmemGemm g;
  float ep[64 * 132];  // epilogue half-tile (64 rows x 128 cols, padded stride 132)
};

__device__ __forceinline__ void mma16816(float* d, const unsigned* a, const unsigned* b) {
  asm volatile(
      "mma.sync.aligned.m16n8k16.row.col.f32.bf16.bf16.f32 "
      "{%0,%1,%2,%3}, {%4,%5,%6,%7}, {%8,%9}, {%0,%1,%2,%3};\n"
      : "+f"(d[0]), "+f"(d[1]), "+f"(d[2]), "+f"(d[3])
      : "r"(a[0]), "r"(a[1]), "r"(a[2]), "r"(a[3]), "r"(b[0]), "r"(b[1]));
}

// fp32 -> (hi, lo) bf16 split; 3 cross-products recover ~16-bit mantissa accuracy
__device__ __forceinline__ void split4(float4 v, __nv_bfloat16* hi, __nv_bfloat16* lo) {
  float x[4] = {v.x, v.y, v.z, v.w};
#pragma unroll
  for (int q = 0; q < 4; q++) {
    __nv_bfloat16 h = __float2bfloat16(x[q]);
    hi[q] = h;
    lo[q] = __float2bfloat16(x[q] - __bfloat162float(h));
  }
}

__device__ __forceinline__ float sigmoidf_(float x) { return 1.0f / (1.0f + expf(-x)); }

// One BK-chunk of the 128x128 warp-tiled GEMM (8 warps: wm in {0,1} x wn in {0..3};
// warp tile 64x32 = 4x4 m16n8 fragments). acc += Ahi*Bhi + Ahi*Blo + Alo*Bhi.
__device__ __forceinline__ void gemm_chunk(const SmemGemm& s, float acc[4][4][4],
                                           int wm, int wn, int lane) {
  const int qr = lane >> 2;
  const int qc = (lane & 3) << 1;
#pragma unroll
  for (int kk = 0; kk < BK; kk += 16) {
    unsigned ah[4][4], al[4][4], bh[4][2], bl[4][2];
#pragma unroll
    for (int mi = 0; mi < 4; mi++) {
      int r = wm * 64 + mi * 16 + qr;
      ah[mi][0] = *(const unsigned*)&s.a_hi[r][kk + qc];
      ah[mi][1] = *(const unsigned*)&s.a_hi[r + 8][kk + qc];
      ah[mi][2] = *(const unsigned*)&s.a_hi[r][kk + qc + 8];
      ah[mi][3] = *(const unsigned*)&s.a_hi[r + 8][kk + qc + 8];
      al[mi][0] = *(const unsigned*)&s.a_lo[r][kk + qc];
      al[mi][1] = *(const unsigned*)&s.a_lo[r + 8][kk + qc];
      al[mi][2] = *(const unsigned*)&s.a_lo[r][kk + qc + 8];
      al[mi][3] = *(const unsigned*)&s.a_lo[r + 8][kk + qc + 8];
    }
#pragma unroll
    for (int ni = 0; ni < 4; ni++) {
      int c = wn * 32 + ni * 8 + qr;
      bh[ni][0] = *(const unsigned*)&s.b_hi[c][kk + qc];
      bh[ni][1] = *(const unsigned*)&s.b_hi[c][kk + qc + 8];
      bl[ni][0] = *(const unsigned*)&s.b_lo[c][kk + qc];
      bl[ni][1] = *(const unsigned*)&s.b_lo[c][kk + qc + 8];
    }
#pragma unroll
    for (int mi = 0; mi < 4; mi++)
#pragma unroll
      for (int ni = 0; ni < 4; ni++) {
        mma16816(acc[mi][ni], ah[mi], bh[ni]);
        mma16816(acc[mi][ni], ah[mi], bl[ni]);
        mma16816(acc[mi][ni], al[mi], bh[ni]);
      }
  }
}

// Store one 64-row half (phase p) of the accumulator tile into su.ep
__device__ __forceinline__ void store_acc_phase(SmemU& su, float acc[4][4][4],
                                                int wm, int wn, int lane, int p) {
  if (wm == p) {
    const int qr = lane >> 2;
    const int qc = (lane & 3) << 1;
#pragma unroll
    for (int mi = 0; mi < 4; mi++)
#pragma unroll
      for (int ni = 0; ni < 4; ni++) {
        int rr = mi * 16 + qr;
        int cc = wn * 32 + ni * 8 + qc;
        su.ep[rr * 132 + cc] = acc[mi][ni][0];
        su.ep[rr * 132 + cc + 1] = acc[mi][ni][1];
        su.ep[(rr + 8) * 132 + cc] = acc[mi][ni][2];
        su.ep[(rr + 8) * 132 + cc + 1] = acc[mi][ni][3];
      }
  }
}

// ---------------------------------------------------------------------------
// Kernel 1: Xpre[z][l][n][4H] = x[z][n][l][:] @ Wih_z^T + (bih_z + bhh_z)
// grid: (colTile=8, rowTile=1024, z=2), rows indexed r = n*8 + l over [N*L]
// ---------------------------------------------------------------------------
__global__ __launch_bounds__(NTHREADS, 1) void k_precompute(
    const float* __restrict__ xl, const float* __restrict__ xr,
    const float* __restrict__ Wih_l, const float* __restrict__ Wih_r,
    const float* __restrict__ bih_l, const float* __restrict__ bhh_l,
    const float* __restrict__ bih_r, const float* __restrict__ bhh_r) {
  __shared__ SmemU su;
  const int tid = threadIdx.x;
  const int z = blockIdx.z;
  const int colTile = blockIdx.x;
  const long rowBase = (long)blockIdx.y * BM;
  const float* A = z ? xr : xl;
  const float* B = z ? Wih_r : Wih_l;
  const float* bi = z ? bih_r : bih_l;
  const float* bhb = z ? bhh_r : bhh_l;

  const int wid = tid >> 5, lane = tid & 31;
  const int wm = wid & 1, wn = wid >> 1;

  float acc[4][4][4];
#pragma unroll
  for (int a = 0; a < 4; a++)
#pragma unroll
    for (int b = 0; b < 4; b++)
#pragma unroll
      for (int q = 0; q < 4; q++) acc[a][b][q] = 0.0f;

  for (int k0 = 0; k0 < 256; k0 += BK) {
#pragma unroll
    for (int i = 0; i < 4; i++) {
      int f = tid + i * NTHREADS;  // float4 index in 128x32 tile
      int r = f >> 3;
      int c = (f & 7) << 2;
      float4 va = *(const float4*)(A + (rowBase + r) * 256 + k0 + c);
      split4(va, &su.g.a_hi[r][c], &su.g.a_lo[r][c]);
      float4 vb = *(const float4*)(B + (long)(colTile * 128 + r) * 256 + k0 + c);
      split4(vb, &su.g.b_hi[r][c], &su.g.b_lo[r][c]);
    }
    __syncthreads();
    gemm_chunk(su.g, acc, wm, wn, lane);
    __syncthreads();
  }

  for (int p = 0; p < 2; p++) {
    store_acc_phase(su, acc, wm, wn, lane, p);
    __syncthreads();
#pragma unroll
    for (int i = 0; i < 8; i++) {
      int f = tid + i * NTHREADS;  // float4 index in 64x128
      int rl = f >> 5;
      int c4 = (f & 31) << 2;
      float4 v = *(const float4*)&su.ep[rl * 132 + c4];
      int col = colTile * 128 + c4;
      v.x += bi[col] + bhb[col];
      v.y += bi[col + 1] + bhb[col + 1];
      v.z += bi[col + 2] + bhb[col + 2];
      v.w += bi[col + 3] + bhb[col + 3];
      long rg = rowBase + p * 64 + rl;
      long n = rg >> 3;
      int l = (int)(rg & 7);
      *(float4*)(g_X + (((long)z * 8 + l) * 16384 + n) * 1024 + col) = v;
    }
    __syncthreads();
  }
}

// ---------------------------------------------------------------------------
// Kernel 2: step 0 elementwise (h0 = c0 = 0): c = sig(i)*tanh(g); h = sig(o)*tanh(c)
// ---------------------------------------------------------------------------
__global__ void k_step0() {
  long idx = (long)blockIdx.x * 256 + threadIdx.x;  // [0, 2*16384*256)
  long z = idx >> 22;
  long e = idx & 4194303;  // n*256 + j
  long n = e >> 8;
  int j = (int)(e & 255);
  const float* xpre = g_X + z * 8L * 16384 * 1024;
  long xb = n * 1024 + j;
  float gi = xpre[xb];
  float gg = xpre[xb + 512];
  float go = xpre[xb + 768];
  float cn = sigmoidf_(gi) * tanhf(gg);
  g_c[z * 4194304 + e] = cn;
  g_h[(z * 2 + 1) * 4194304 + e] = sigmoidf_(go) * tanhf(cn);
}

// ---------------------------------------------------------------------------
// Kernel 3: recurrent step t (t=1..7): gates = h_{t-1}@Whh^T + Xpre[t]; cell update.
// grid: (strip=8, rowTile=128, z=2). CTA gate-column tile = 4 gates x 32 hidden units.
// h double-buffered: read buf[t&1], write buf[(t+1)&1]; c in place.
// ---------------------------------------------------------------------------
__global__ __launch_bounds__(NTHREADS, 1) void k_step(
    const float* __restrict__ Whh_l, const float* __restrict__ Whh_r, int t) {
  __shared__ SmemU su;
  const int tid = threadIdx.x;
  const int z = blockIdx.z;
  const int strip = blockIdx.x;
  const long rowBase = (long)blockIdx.y * BM;
  const float* B = z ? Whh_r : Whh_l;
  const float* hprev = g_h + ((long)z * 2 + (t & 1)) * 4194304;
  float* hnext = g_h + ((long)z * 2 + ((t + 1) & 1)) * 4194304;
  float* cst = g_c + (long)z * 4194304;
  const float* xpre = g_X + ((long)z * 8 + t) * 16384L * 1024;

  const int wid = tid >> 5, lane = tid & 31;
  const int wm = wid & 1, wn = wid >> 1;

  float acc[4][4][4];
#pragma unroll
  for (int a = 0; a < 4; a++)
#pragma unroll
    for (int b = 0; b < 4; b++)
#pragma unroll
      for (int q = 0; q < 4; q++) acc[a][b][q] = 0.0f;

  for (int k0 = 0; k0 < 256; k0 += BK) {
#pragma unroll
    for (int i = 0; i < 4; i++) {
      int f = tid + i * NTHREADS;
      int r = f >> 3;
      int c = (f & 7) << 2;
      float4 va = *(const float4*)(hprev + (rowBase + r) * 256 + k0 + c);
      split4(va, &su.g.a_hi[r][c], &su.g.a_lo[r][c]);
      // B tile row r -> Whh row = gate*256 + strip*32 + (r&31)
      long brow = (long)((r >> 5) << 8) + strip * 32 + (r & 31);
      float4 vb = *(const float4*)(B + brow * 256 + k0 + c);
      split4(vb, &su.g.b_hi[r][c], &su.g.b_lo[r][c]);
    }
    __syncthreads();
    gemm_chunk(su.g, acc, wm, wn, lane);
    __syncthreads();
  }

  for (int p = 0; p < 2; p++) {
    store_acc_phase(su, acc, wm, wn, lane, p);
    __syncthreads();
#pragma unroll
    for (int i = 0; i < 8; i++) {
      int e = tid + i * NTHREADS;  // 64 rows x 32 hidden units
      int rl = e >> 5;
      int jj = e & 31;
      long n = rowBase + p * 64 + rl;
      int j = strip * 32 + jj;
      long xb = n * 1024 + j;
      float gi = su.ep[rl * 132 + jj] + xpre[xb];
      float gf = su.ep[rl * 132 + 32 + jj] + xpre[xb + 256];
      float gg = su.ep[rl * 132 + 64 + jj] + xpre[xb + 512];
      float go = su.ep[rl * 132 + 96 + jj] + xpre[xb + 768];
      float cn = sigmoidf_(gf) * cst[n * 256 + j] + sigmoidf_(gi) * tanhf(gg);
      cst[n * 256 + j] = cn;
      hnext[n * 256 + j] = sigmoidf_(go) * tanhf(cn);
    }
    __syncthreads();
  }
}

// ---------------------------------------------------------------------------
// Kernel 4: encoder out = tanh([hl, hr, rel] @ Wenc^T + benc)
// grid: (colTile=2, rowTile=128). K = 576 gathered from 3 sources.
// Final h lives in buf 0 for both LSTMs (after t=7 write).
// ---------------------------------------------------------------------------
__global__ __launch_bounds__(NTHREADS, 1) void k_enc(
    const float* __restrict__ rel, const float* __restrict__ Wenc,
    const float* __restrict__ benc, float* __restrict__ out) {
  __shared__ SmemU su;
  const int tid = threadIdx.x;
  const int colTile = blockIdx.x;
  const long rowBase = (long)blockIdx.y * BM;
  const float* hL = g_h;                   // z=0, buf 0
  const float* hR = g_h + 2L * 4194304;    // z=1, buf 0

  const int wid = tid >> 5, lane = tid & 31;
  const int wm = wid & 1, wn = wid >> 1;

  float acc[4][4][4];
#pragma unroll
  for (int a = 0; a < 4; a++)
#pragma unroll
    for (int b = 0; b < 4; b++)
#pragma unroll
      for (int q = 0; q < 4; q++) acc[a][b][q] = 0.0f;

  for (int k0 = 0; k0 < 576; k0 += BK) {
    const float* Asrc;
    long lda, koff;
    if (k0 < 256) {
      Asrc = hL; lda = 256; koff = k0;
    } else if (k0 < 512) {
      Asrc = hR; lda = 256; koff = k0 - 256;
    } else {
      Asrc = rel; lda = 64; koff = k0 - 512;
    }
#pragma unroll
    for (int i = 0; i < 4; i++) {
      int f = tid + i * NTHREADS;
      int r = f >> 3;
      int c = (f & 7) << 2;
      float4 va = *(const float4*)(Asrc + (rowBase + r) * lda + koff + c);
      split4(va, &su.g.a_hi[r][c], &su.g.a_lo[r][c]);
      float4 vb = *(const float4*)(Wenc + (long)(colTile * 128 + r) * 576 + k0 + c);
      split4(vb, &su.g.b_hi[r][c], &su.g.b_lo[r][c]);
    }
    __syncthreads();
    gemm_chunk(su.g, acc, wm, wn, lane);
    __syncthreads();
  }

  for (int p = 0; p < 2; p++) {
    store_acc_phase(su, acc, wm, wn, lane, p);
    __syncthreads();
#pragma unroll
    for (int i = 0; i < 8; i++) {
      int f = tid + i * NTHREADS;
      int rl = f >> 5;
      int c4 = (f & 31) << 2;
      float4 v = *(const float4*)&su.ep[rl * 132 + c4];
      int col = colTile * 128 + c4;
      v.x = tanhf(v.x + benc[col]);
      v.y = tanhf(v.y + benc[col + 1]);
      v.z = tanhf(v.z + benc[col + 2]);
      v.w = tanhf(v.w + benc[col + 3]);
      long n = rowBase + p * 64 + rl;
      *(float4*)(out + n * 256 + col) = v;
    }
    __syncthreads();
  }
}

// ---------------------------------------------------------------------------
extern "C" void kernel_launch(void* const* d_in, const int* in_sizes, int n_in,
                              void* d_out, int out_size) {
  (void)in_sizes; (void)n_in; (void)out_size;
  const float* left  = (const float*)d_in[0];
  const float* right = (const float*)d_in[1];
  const float* rel   = (const float*)d_in[2];
  const float* Wih_l = (const float*)d_in[3];
  const float* Whh_l = (const float*)d_in[4];
  const float* bih_l = (const float*)d_in[5];
  const float* bhh_l = (const float*)d_in[6];
  const float* Wih_r = (const float*)d_in[7];
  const float* Whh_r = (const float*)d_in[8];
  const float* bih_r = (const float*)d_in[9];
  const float* bhh_r = (const float*)d_in[10];
  const float* Wenc  = (const float*)d_in[11];
  const float* benc  = (const float*)d_in[12];
  float* out = (float*)d_out;

  k_precompute<<<dim3(8, 1024, 2), NTHREADS>>>(left, right, Wih_l, Wih_r,
                                               bih_l, bhh_l, bih_r, bhh_r);
  k_step0<<<32768, 256>>>();
  for (int t = 1; t < 8; t++)
    k_step<<<dim3(8, 128, 2), NTHREADS>>>(Whh_l, Whh_r, t);
  k_enc<<<dim3(2, 128), NTHREADS>>>(rel, Wenc, benc, out);
}